// round 6
// baseline (speedup 1.0000x reference)
#include <cuda_runtime.h>
#include <cuda_fp16.h>
#include <cstdint>

// Problem constants
#define Bq 8
#define Dd 256
#define Tt 2048
#define Kk 8192
#define NQ (Bq * Tt)          // 16384 queries
#define NEL (Bq * Dd * Tt)    // 4194304 z elements
#define NGRP (Kk / 8)         // 1024 groups of 8 codes

#define EPS 0.006f
#define CAND_CAP (2 * 1024 * 1024)

// Phase-1 tiling
#define PM 128
#define PN 128
#define PK 32
#define ROWB 40               // smem row stride = 40 halves (conflict-free ldmatrix)
#define NSTAGE 3
#define STAGE_HALVES (2 * PM * ROWB)          // A(128 rows) + B(128 rows)
#define STAGE_BYTES  (STAGE_HALVES * 2)       // 20480
#define SMEM_DYN     (NSTAGE * STAGE_BYTES)   // 61440

// Device scratch (static; runtime allocation is forbidden)
__device__ __align__(128) float  g_zt[NQ * Dd];     // z transposed [q][d] fp32
__device__ __align__(128) __half g_zhf[NQ * Dd];    // fp16 copy
__device__ __align__(128) __half g_cbhf[Kk * Dd];   // codebook * 256, fp16
__device__ __align__(128) float  g_gmin[(size_t)NGRP * NQ]; // per-(group,query) approx (cc-2dot)
__device__ __align__(128) unsigned g_m1[NQ];        // per-query encoded min of g_gmin
__device__ __align__(128) float  g_zz[NQ];
__device__ __align__(128) float  g_cc[Kk];
__device__ __align__(128) unsigned long long g_key[NQ];    // packed (dbits<<32)|k exact
__device__ __align__(128) unsigned int g_cand[CAND_CAP];   // (q<<10)|g
__device__ int    g_ncand;
__device__ double g_loss_sum;

// ---------------------------------------------------------------------------
__device__ __forceinline__ uint32_t smem_u32(const void* p) {
    uint32_t a;
    asm("{ .reg .u64 t; cvta.to.shared.u64 t, %1; cvt.u32.u64 %0, t; }" : "=r"(a) : "l"(p));
    return a;
}
// Order-preserving float<->uint encoding (monotone for all finite floats)
__device__ __forceinline__ unsigned fenc(float f) {
    int b = __float_as_int(f);
    return b >= 0 ? ((unsigned)b | 0x80000000u) : ~(unsigned)b;
}
__device__ __forceinline__ float fdec(unsigned k) {
    return (k & 0x80000000u) ? __int_as_float((int)(k & 0x7fffffffu))
                             : __int_as_float((int)~k);
}
#define CP16(dst, src) \
    asm volatile("cp.async.cg.shared.global [%0], [%1], 16;" :: "r"(dst), "l"(src) : "memory")
#define LDM4(r0, r1, r2, r3, a) \
    asm volatile("ldmatrix.sync.aligned.m8n8.x4.shared.b16 {%0,%1,%2,%3}, [%4];" \
        : "=r"(r0), "=r"(r1), "=r"(r2), "=r"(r3) : "r"(a))
#define MMA16816(c0, c1, c2, c3, a0, a1, a2, a3, b0, b1) \
    asm volatile("mma.sync.aligned.m16n8k16.row.col.f32.f16.f16.f32 " \
        "{%0,%1,%2,%3}, {%4,%5,%6,%7}, {%8,%9}, {%0,%1,%2,%3};" \
        : "+f"(c0), "+f"(c1), "+f"(c2), "+f"(c3) \
        : "r"(a0), "r"(a1), "r"(a2), "r"(a3), "r"(b0), "r"(b1))

// ---------------------------------------------------------------------------
// Exact sequential fp32 sums of squares (rounding order validated in R1)
__global__ void zz_kernel(const float* __restrict__ z) {
    int i = blockIdx.x * blockDim.x + threadIdx.x;
    if (i >= NQ) return;
    int b = i / Tt, t = i % Tt;
    const float* p = z + (size_t)b * Dd * Tt + t;
    float acc = 0.0f;
    for (int d = 0; d < Dd; d++) {
        float v = p[(size_t)d * Tt];
        acc = __fadd_rn(acc, __fmul_rn(v, v));
    }
    g_zz[i] = acc;
}

// cc (exact sequential) + global init fused (runs before phase1)
__global__ void cc_init_kernel(const float* __restrict__ cb) {
    int i = blockIdx.x * blockDim.x + threadIdx.x;
    if (i < Kk) {
        const float* p = cb + (size_t)i * Dd;
        float acc = 0.0f;
        for (int d = 0; d < Dd; d++) {
            float v = p[d];
            acc = __fadd_rn(acc, __fmul_rn(v, v));
        }
        g_cc[i] = acc;
    }
    if (i < NQ) { g_key[i] = ~0ull; g_m1[i] = 0xFFFFFFFFu; }
    if (i == 0) { g_loss_sum = 0.0; g_ncand = 0; }
}

// codebook * 256 (exact pow2 rescale into fp16's sweet spot)
__global__ void prep_cb_kernel(const float* __restrict__ cb) {
    int i = blockIdx.x * blockDim.x + threadIdx.x;
    if (i < Kk * Dd) g_cbhf[i] = __float2half(cb[i] * 256.0f);
}

// Transpose z (B,D,T) -> [q][d]; write fp32 + fp16 copies.
__global__ void prep_z_kernel(const float* __restrict__ z) {
    __shared__ float tile[32][33];
    int b = blockIdx.z, t0 = blockIdx.x * 32, d0 = blockIdx.y * 32;
    int tx = threadIdx.x, ty = threadIdx.y;   // 32 x 8
    #pragma unroll
    for (int r = 0; r < 4; r++) {
        int d = d0 + ty + r * 8;
        tile[ty + r * 8][tx] = z[(size_t)b * Dd * Tt + (size_t)d * Tt + t0 + tx];
    }
    __syncthreads();
    #pragma unroll
    for (int r = 0; r < 4; r++) {
        int tt = t0 + ty + r * 8;
        float v = tile[tx][ty + r * 8];
        size_t o = (size_t)(b * Tt + tt) * Dd + d0 + tx;
        g_zt[o] = v;
        g_zhf[o] = __float2half(v);
    }
}

// ---------------------------------------------------------------------------
// Phase 1: fp16 mma.sync GEMM. 3-stage cp.async pipeline; per chunk all 12
// ldmatrix fragments prefetched before the 32 MMAs (LDS/tensor overlap).
// Epilogue: per-(query, 8-code-group) min of (cc - 2*dot) -> g_gmin, plus
// per-query running min -> g_m1 (smem atomics + 1 global atomicMin per row).
__global__ void __launch_bounds__(256) phase1_kernel() {
    extern __shared__ __half smh[];
    __shared__ unsigned srowmin[PM];

    int tid = threadIdx.x, wid = tid >> 5, l = tid & 31;
    int wm = wid & 3, wn = wid >> 2;
    int q0 = blockIdx.y * PM, k0 = blockIdx.x * PN;

    if (tid < PM) srowmin[tid] = 0xFFFFFFFFu;

    float acc[2][8][4];
    #pragma unroll
    for (int mi = 0; mi < 2; mi++)
        #pragma unroll
        for (int ni = 0; ni < 8; ni++)
            #pragma unroll
            for (int j = 0; j < 4; j++) acc[mi][ni][j] = 0.0f;

    int arow[2], ac4[2];
    #pragma unroll
    for (int i = 0; i < 2; i++) {
        int idx = tid + i * 256;
        arow[i] = idx >> 2; ac4[i] = idx & 3;
    }
    uint32_t s0 = smem_u32(&smh[0]);
    const uint32_t bOffB = PM * ROWB * 2;     // B region offset within a stage

    int rA = wm * 32 + (l & 15), hA = (l >> 4) & 1;
    int rB = wn * 64 + (l & 15), hB = (l >> 4) & 1;
    uint32_t aoff = (uint32_t)(rA * ROWB + hA * 8) * 2;
    uint32_t boff = (uint32_t)(rB * ROWB + hB * 8) * 2;

    auto issue = [&](int c) {
        uint32_t st = s0 + (uint32_t)(c % NSTAGE) * STAGE_BYTES;
        int d0 = c * PK;
        #pragma unroll
        for (int i = 0; i < 2; i++) {
            uint32_t off = (uint32_t)(arow[i] * ROWB + ac4[i] * 8) * 2;
            CP16(st + off, g_zhf + (size_t)(q0 + arow[i]) * Dd + d0 + ac4[i] * 8);
            CP16(st + bOffB + off, g_cbhf + (size_t)(k0 + arow[i]) * Dd + d0 + ac4[i] * 8);
        }
        asm volatile("cp.async.commit_group;" ::: "memory");
    };

    issue(0); issue(1);
    for (int c = 0; c < 8; c++) {
        if (c + 2 < 8) {
            issue(c + 2);
            asm volatile("cp.async.wait_group 2;" ::: "memory");
        } else if (c == 6) {
            asm volatile("cp.async.wait_group 1;" ::: "memory");
        } else {
            asm volatile("cp.async.wait_group 0;" ::: "memory");
        }
        __syncthreads();
        uint32_t st = s0 + (uint32_t)(c % NSTAGE) * STAGE_BYTES;
        uint32_t bA = st, bB = st + bOffB;

        // Prefetch ALL fragments for this chunk (both ks halves)
        uint32_t af[2][2][4], bf[2][4][4];
        #pragma unroll
        for (int ks = 0; ks < 2; ks++)
            #pragma unroll
            for (int mi = 0; mi < 2; mi++)
                LDM4(af[mi][ks][0], af[mi][ks][1], af[mi][ks][2], af[mi][ks][3],
                     bA + aoff + (uint32_t)(mi * 16 * ROWB + ks * 16) * 2);
        #pragma unroll
        for (int ks = 0; ks < 2; ks++)
            #pragma unroll
            for (int p = 0; p < 4; p++)
                LDM4(bf[ks][p][0], bf[ks][p][1], bf[ks][p][2], bf[ks][p][3],
                     bB + boff + (uint32_t)(p * 16 * ROWB + ks * 16) * 2);
        __syncthreads();   // stage free for reuse; MMAs below overlap cp.async

        #pragma unroll
        for (int ks = 0; ks < 2; ks++)
            #pragma unroll
            for (int mi = 0; mi < 2; mi++)
                #pragma unroll
                for (int p = 0; p < 4; p++) {
                    MMA16816(acc[mi][2*p][0], acc[mi][2*p][1], acc[mi][2*p][2], acc[mi][2*p][3],
                             af[mi][ks][0], af[mi][ks][1], af[mi][ks][2], af[mi][ks][3],
                             bf[ks][p][0], bf[ks][p][2]);
                    MMA16816(acc[mi][2*p+1][0], acc[mi][2*p+1][1], acc[mi][2*p+1][2], acc[mi][2*p+1][3],
                             af[mi][ks][0], af[mi][ks][1], af[mi][ks][2], af[mi][ks][3],
                             bf[ks][p][1], bf[ks][p][3]);
                }
    }

    // Epilogue: v = cc - 2*dot = fma(acc, -2^-7, cc)  (acc = dot*256)
    int gq = l >> 2;
    #pragma unroll
    for (int mi = 0; mi < 2; mi++) {
        int rl0 = wm * 32 + mi * 16 + gq;       // local row, and rl0+8
        float rmin0 = 3.4e38f, rmin8 = 3.4e38f;
        #pragma unroll
        for (int ni = 0; ni < 8; ni++) {
            int col = k0 + wn * 64 + ni * 8 + (l & 3) * 2;
            float cc0 = g_cc[col], cc1 = g_cc[col + 1];
            float m0 = fminf(fmaf(acc[mi][ni][0], -0.0078125f, cc0),
                             fmaf(acc[mi][ni][1], -0.0078125f, cc1));
            float m8 = fminf(fmaf(acc[mi][ni][2], -0.0078125f, cc0),
                             fmaf(acc[mi][ni][3], -0.0078125f, cc1));
            m0 = fminf(m0, __shfl_xor_sync(~0u, m0, 1));
            m0 = fminf(m0, __shfl_xor_sync(~0u, m0, 2));
            m8 = fminf(m8, __shfl_xor_sync(~0u, m8, 1));
            m8 = fminf(m8, __shfl_xor_sync(~0u, m8, 2));
            if ((l & 3) == 0) {
                size_t g = (size_t)((k0 + wn * 64 + ni * 8) >> 3);
                g_gmin[g * NQ + q0 + rl0] = m0;
                g_gmin[g * NQ + q0 + rl0 + 8] = m8;
                rmin0 = fminf(rmin0, m0);
                rmin8 = fminf(rmin8, m8);
            }
        }
        if ((l & 3) == 0) {
            atomicMin(&srowmin[rl0], fenc(rmin0));
            atomicMin(&srowmin[rl0 + 8], fenc(rmin8));
        }
    }
    __syncthreads();
    if (tid < PM) atomicMin(&g_m1[q0 + tid], srowmin[tid]);
}

// ---------------------------------------------------------------------------
// Phase 2a: flag groups with v <= m1 + EPS (single pass; m1 from phase1).
__global__ void __launch_bounds__(256) cand_kernel() {
    int q0 = blockIdx.x * 32;
    int wid = threadIdx.x >> 5, l = threadIdx.x & 31;
    int q = q0 + l;
    float thr = fdec(g_m1[q]) + EPS;
    for (int g = wid; g < NGRP; g += 8) {
        if (g_gmin[(size_t)g * NQ + q] <= thr) {
            int pos = atomicAdd(&g_ncand, 1);
            if (pos < CAND_CAP) g_cand[pos] = ((unsigned)q << 10) | (unsigned)g;
        }
    }
}

// Phase 2b: exact fp32 rescore of flagged groups; packed atomicMin => argmin
// with first-index tie-break (reference rounding formula, R1-validated).
__global__ void __launch_bounds__(256) rescore_kernel(const float* __restrict__ cb) {
    int gw = (blockIdx.x * blockDim.x + threadIdx.x) >> 5;
    int l = threadIdx.x & 31;
    int nwarps = (gridDim.x * blockDim.x) >> 5;
    int n = g_ncand; if (n > CAND_CAP) n = CAND_CAP;
    for (int c = gw; c < n; c += nwarps) {
        unsigned e = g_cand[c];
        int q = e >> 10, g = e & 1023;
        const float* zr = g_zt + (size_t)q * Dd;
        float zzv = g_zz[q];
        unsigned long long best = ~0ull;
        #pragma unroll 1
        for (int kk = 0; kk < 8; kk++) {
            int k = g * 8 + kk;
            const float* cr = cb + (size_t)k * Dd;
            float p = 0.0f;
            #pragma unroll
            for (int j = 0; j < 8; j++) {
                int d = l * 8 + j;
                p = __fadd_rn(p, __fmul_rn(zr[d], cr[d]));
            }
            #pragma unroll
            for (int o = 16; o > 0; o >>= 1)
                p = __fadd_rn(p, __shfl_xor_sync(~0u, p, o));
            float dd = __fadd_rn(__fadd_rn(zzv, __fmul_rn(-2.0f, p)), g_cc[k]);
            unsigned long long key =
                ((unsigned long long)__float_as_uint(dd) << 32) | (unsigned)k;
            if (key < best) best = key;
        }
        if (l == 0) atomicMin(&g_key[q], best);
    }
}

// ---------------------------------------------------------------------------
// Gather: coalesced via smem transpose of the gathered codebook rows.
__global__ void gather_kernel(const float* __restrict__ z,
                              const float* __restrict__ cb,
                              float* __restrict__ out, long long out_size) {
    __shared__ float tile[32][33];
    __shared__ double ssum[256];
    int b = blockIdx.z, d0 = blockIdx.y * 32, t0 = blockIdx.x * 32;
    int tx = threadIdx.x, ty = threadIdx.y;
    #pragma unroll
    for (int r = 0; r < 4; r++) {
        int t = ty + r * 8;
        int q = b * Tt + t0 + t;
        int idx = (int)(unsigned)(g_key[q] & 0xffffffffu);
        tile[t][tx] = cb[(size_t)idx * Dd + d0 + tx];     // lane spans d: coalesced
    }
    __syncthreads();
    double local = 0.0;
    #pragma unroll
    for (int r = 0; r < 4; r++) {
        int d = d0 + ty + r * 8;
        long long o = ((long long)b * Dd + d) * Tt + t0 + tx;
        float zv = z[o];
        float zq = tile[tx][ty + r * 8];
        float diff = __fadd_rn(zq, -zv);
        if (o < out_size) out[o] = __fadd_rn(zv, diff);   // lane spans t: coalesced
        local += (double)__fmul_rn(diff, diff);
    }
    int tid = ty * 32 + tx;
    ssum[tid] = local;
    __syncthreads();
    for (int s = 128; s > 0; s >>= 1) {
        if (tid < s) ssum[tid] += ssum[tid + s];
        __syncthreads();
    }
    if (tid == 0) atomicAdd(&g_loss_sum, ssum[0]);
}

__global__ void finalize_kernel(float* __restrict__ out, long long out_size) {
    int i = blockIdx.x * blockDim.x + threadIdx.x;
    if (out_size >= NEL + NQ && i < NQ)
        out[NEL + i] = (float)(unsigned)(g_key[i] & 0xffffffffu);
    if (i == 0 && out_size >= NEL + NQ + 1) {
        float m = (float)(g_loss_sum / (double)NEL);
        out[NEL + NQ] = __fadd_rn(m, __fmul_rn(0.1f, m));
    }
}

// ---------------------------------------------------------------------------
extern "C" void kernel_launch(void* const* d_in, const int* in_sizes, int n_in,
                              void* d_out, int out_size) {
    const float* z  = (const float*)d_in[0];
    const float* cb = (const float*)d_in[1];
    if (n_in >= 2 && in_sizes[0] == Kk * Dd && in_sizes[1] == NEL) {
        const float* tmp = z; z = cb; cb = tmp;
    }
    float* out = (float*)d_out;
    long long osz = out_size;

    cudaFuncSetAttribute(phase1_kernel,
                         cudaFuncAttributeMaxDynamicSharedMemorySize, SMEM_DYN);

    // phase1 kept at launch index 3 (the launch ncu captures)
    prep_cb_kernel<<<(Kk * Dd + 255) / 256, 256>>>(cb);                 // 0
    dim3 tb(32, 8), tg(Tt / 32, Dd / 32, Bq);
    prep_z_kernel<<<tg, tb>>>(z);                                       // 1
    cc_init_kernel<<<(NQ + 255) / 256, 256>>>(cb);                      // 2
    dim3 g1(Kk / PN, NQ / PM);
    phase1_kernel<<<g1, 256, SMEM_DYN>>>();                             // 3
    zz_kernel<<<(NQ + 255) / 256, 256>>>(z);                            // 4
    cand_kernel<<<NQ / 32, 256>>>();                                    // 5
    rescore_kernel<<<512, 256>>>(cb);                                   // 6
    dim3 gg(Tt / 32, Dd / 32, Bq);
    gather_kernel<<<gg, tb>>>(z, cb, out, osz);                         // 7
    finalize_kernel<<<(NQ + 255) / 256, 256>>>(out, osz);               // 8
}

// round 7
// speedup vs baseline: 1.0463x; 1.0463x over previous
#include <cuda_runtime.h>
#include <cuda_fp16.h>
#include <cstdint>

// Problem constants
#define Bq 8
#define Dd 256
#define Tt 2048
#define Kk 8192
#define NQ (Bq * Tt)          // 16384 queries
#define NEL (Bq * Dd * Tt)    // 4194304 z elements
#define NGRP (Kk / 8)         // 1024 groups of 8 codes

#define EPS 0.006f
#define CAND_CAP (2 * 1024 * 1024)

// Phase-1 tiling
#define PM 128
#define PN 128
#define PK 64                 // gemm-K chunk (halved sync count vs PK=32)
#define NCHUNK (Dd / PK)      // 4
#define ROWB 72               // smem row stride = 72 halves (64 data + 8 pad)
#define STAGE_BYTES ((PM + PN) * ROWB * 2)    // 36864
#define SMEM_DYN (2 * STAGE_BYTES)            // 73728

// Device scratch (static; runtime allocation is forbidden)
__device__ __align__(128) float  g_zt[NQ * Dd];     // z transposed [q][d] fp32
__device__ __align__(128) __half g_zhf[NQ * Dd];    // fp16 copy
__device__ __align__(128) __half g_cbhf[Kk * Dd];   // codebook * 256, fp16
__device__ __align__(128) float  g_gmin[(size_t)NGRP * NQ]; // per-(group,query) approx (cc-2dot)
__device__ __align__(128) unsigned g_m1[NQ];        // per-query encoded min of g_gmin
__device__ __align__(128) float  g_zz[NQ];
__device__ __align__(128) float  g_cc[Kk];
__device__ __align__(128) unsigned long long g_key[NQ];    // packed (dbits<<32)|k exact
__device__ __align__(128) unsigned int g_cand[CAND_CAP];   // (q<<10)|g
__device__ int    g_ncand;
__device__ double g_loss_sum;

// ---------------------------------------------------------------------------
__device__ __forceinline__ uint32_t smem_u32(const void* p) {
    uint32_t a;
    asm("{ .reg .u64 t; cvta.to.shared.u64 t, %1; cvt.u32.u64 %0, t; }" : "=r"(a) : "l"(p));
    return a;
}
// Order-preserving float<->uint encoding (monotone for all finite floats)
__device__ __forceinline__ unsigned fenc(float f) {
    int b = __float_as_int(f);
    return b >= 0 ? ((unsigned)b | 0x80000000u) : ~(unsigned)b;
}
__device__ __forceinline__ float fdec(unsigned k) {
    return (k & 0x80000000u) ? __int_as_float((int)(k & 0x7fffffffu))
                             : __int_as_float((int)~k);
}
#define CP16(dst, src) \
    asm volatile("cp.async.cg.shared.global [%0], [%1], 16;" :: "r"(dst), "l"(src) : "memory")
#define LDM4(r0, r1, r2, r3, a) \
    asm volatile("ldmatrix.sync.aligned.m8n8.x4.shared.b16 {%0,%1,%2,%3}, [%4];" \
        : "=r"(r0), "=r"(r1), "=r"(r2), "=r"(r3) : "r"(a))
#define MMA16816(c0, c1, c2, c3, a0, a1, a2, a3, b0, b1) \
    asm volatile("mma.sync.aligned.m16n8k16.row.col.f32.f16.f16.f32 " \
        "{%0,%1,%2,%3}, {%4,%5,%6,%7}, {%8,%9}, {%0,%1,%2,%3};" \
        : "+f"(c0), "+f"(c1), "+f"(c2), "+f"(c3) \
        : "r"(a0), "r"(a1), "r"(a2), "r"(a3), "r"(b0), "r"(b1))

// ---------------------------------------------------------------------------
// Exact sequential fp32 sums of squares (rounding order validated in R1)
__global__ void zz_kernel(const float* __restrict__ z) {
    int i = blockIdx.x * blockDim.x + threadIdx.x;
    if (i >= NQ) return;
    int b = i / Tt, t = i % Tt;
    const float* p = z + (size_t)b * Dd * Tt + t;
    float acc = 0.0f;
    for (int d = 0; d < Dd; d++) {
        float v = p[(size_t)d * Tt];
        acc = __fadd_rn(acc, __fmul_rn(v, v));
    }
    g_zz[i] = acc;
}

// cc (exact sequential) + global init fused
__global__ void cc_init_kernel(const float* __restrict__ cb) {
    int i = blockIdx.x * blockDim.x + threadIdx.x;
    if (i < Kk) {
        const float* p = cb + (size_t)i * Dd;
        float acc = 0.0f;
        for (int d = 0; d < Dd; d++) {
            float v = p[d];
            acc = __fadd_rn(acc, __fmul_rn(v, v));
        }
        g_cc[i] = acc;
    }
    if (i < NQ) { g_key[i] = ~0ull; g_m1[i] = 0xFFFFFFFFu; }
    if (i == 0) { g_loss_sum = 0.0; g_ncand = 0; }
}

// codebook * 256 (exact pow2 rescale into fp16's sweet spot)
__global__ void prep_cb_kernel(const float* __restrict__ cb) {
    int i = blockIdx.x * blockDim.x + threadIdx.x;
    if (i < Kk * Dd) g_cbhf[i] = __float2half(cb[i] * 256.0f);
}

// Transpose z (B,D,T) -> [q][d]; write fp32 + fp16 copies.
__global__ void prep_z_kernel(const float* __restrict__ z) {
    __shared__ float tile[32][33];
    int b = blockIdx.z, t0 = blockIdx.x * 32, d0 = blockIdx.y * 32;
    int tx = threadIdx.x, ty = threadIdx.y;   // 32 x 8
    #pragma unroll
    for (int r = 0; r < 4; r++) {
        int d = d0 + ty + r * 8;
        tile[ty + r * 8][tx] = z[(size_t)b * Dd * Tt + (size_t)d * Tt + t0 + tx];
    }
    __syncthreads();
    #pragma unroll
    for (int r = 0; r < 4; r++) {
        int tt = t0 + ty + r * 8;
        float v = tile[tx][ty + r * 8];
        size_t o = (size_t)(b * Tt + tt) * Dd + d0 + tx;
        g_zt[o] = v;
        g_zhf[o] = __float2half(v);
    }
}

// ---------------------------------------------------------------------------
// Phase 1: fp16 mma.sync GEMM (R5 register structure, PK=64 chunks).
// 2-stage cp.async double buffer; fragments loaded per-ks (small live set).
// Epilogue: per-(query, 8-code-group) min -> g_gmin, per-query min -> g_m1.
__global__ void __launch_bounds__(256, 2) phase1_kernel() {
    extern __shared__ __half smh[];
    __shared__ unsigned srowmin[PM];

    int tid = threadIdx.x, wid = tid >> 5, l = tid & 31;
    int wm = wid & 3, wn = wid >> 2;
    int q0 = blockIdx.y * PM, k0 = blockIdx.x * PN;

    if (tid < PM) srowmin[tid] = 0xFFFFFFFFu;

    float acc[2][8][4];
    #pragma unroll
    for (int mi = 0; mi < 2; mi++)
        #pragma unroll
        for (int ni = 0; ni < 8; ni++)
            #pragma unroll
            for (int j = 0; j < 4; j++) acc[mi][ni][j] = 0.0f;

    // cp.async mapping: 2048 16B-chunks/stage (256 rows x 8), 8 per thread
    uint32_t s0 = smem_u32(&smh[0]);
    const uint32_t bOffB = (uint32_t)PM * ROWB * 2;

    int rA = wm * 32 + (l & 15), hA = (l >> 4) & 1;
    int rB = wn * 64 + (l & 15), hB = (l >> 4) & 1;
    uint32_t aoff = (uint32_t)(rA * ROWB + hA * 8) * 2;
    uint32_t boff = (uint32_t)(rB * ROWB + hB * 8) * 2;

    auto issue = [&](int c) {
        uint32_t st = s0 + (uint32_t)(c & 1) * STAGE_BYTES;
        int d0 = c * PK;
        #pragma unroll
        for (int i = 0; i < 8; i++) {
            int idx = tid + i * 256;          // 0..2047
            int row = idx >> 3, sec = idx & 7;
            uint32_t off = (uint32_t)(row * ROWB + sec * 8) * 2;
            const __half* src = (row < PM)
                ? g_zhf + (size_t)(q0 + row) * Dd + d0 + sec * 8
                : g_cbhf + (size_t)(k0 + row - PM) * Dd + d0 + sec * 8;
            uint32_t dst = st + ((row < PM) ? off : (bOffB + (uint32_t)((row - PM) * ROWB + sec * 8) * 2));
            CP16(dst, src);
        }
        asm volatile("cp.async.commit_group;" ::: "memory");
    };

    issue(0);
    for (int c = 0; c < NCHUNK; c++) {
        if (c + 1 < NCHUNK) {
            issue(c + 1);
            asm volatile("cp.async.wait_group 1;" ::: "memory");
        } else {
            asm volatile("cp.async.wait_group 0;" ::: "memory");
        }
        __syncthreads();
        uint32_t st = s0 + (uint32_t)(c & 1) * STAGE_BYTES;
        uint32_t bA = st, bB = st + bOffB;
        #pragma unroll
        for (int ks = 0; ks < 4; ks++) {           // 4 x k16 within the 64-chunk
            uint32_t af[2][4], bf[4][4];
            #pragma unroll
            for (int mi = 0; mi < 2; mi++)
                LDM4(af[mi][0], af[mi][1], af[mi][2], af[mi][3],
                     bA + aoff + (uint32_t)(mi * 16 * ROWB + ks * 16) * 2);
            #pragma unroll
            for (int p = 0; p < 4; p++)
                LDM4(bf[p][0], bf[p][1], bf[p][2], bf[p][3],
                     bB + boff + (uint32_t)(p * 16 * ROWB + ks * 16) * 2);
            #pragma unroll
            for (int mi = 0; mi < 2; mi++)
                #pragma unroll
                for (int p = 0; p < 4; p++) {
                    MMA16816(acc[mi][2*p][0], acc[mi][2*p][1], acc[mi][2*p][2], acc[mi][2*p][3],
                             af[mi][0], af[mi][1], af[mi][2], af[mi][3],
                             bf[p][0], bf[p][2]);
                    MMA16816(acc[mi][2*p+1][0], acc[mi][2*p+1][1], acc[mi][2*p+1][2], acc[mi][2*p+1][3],
                             af[mi][0], af[mi][1], af[mi][2], af[mi][3],
                             bf[p][1], bf[p][3]);
                }
        }
        __syncthreads();
    }

    // Epilogue: v = cc - 2*dot = fma(acc, -2^-7, cc)  (acc = dot*256)
    int gq = l >> 2;
    #pragma unroll
    for (int mi = 0; mi < 2; mi++) {
        int rl0 = wm * 32 + mi * 16 + gq;
        float rmin0 = 3.4e38f, rmin8 = 3.4e38f;
        #pragma unroll
        for (int ni = 0; ni < 8; ni++) {
            int col = k0 + wn * 64 + ni * 8 + (l & 3) * 2;
            float cc0 = g_cc[col], cc1 = g_cc[col + 1];
            float m0 = fminf(fmaf(acc[mi][ni][0], -0.0078125f, cc0),
                             fmaf(acc[mi][ni][1], -0.0078125f, cc1));
            float m8 = fminf(fmaf(acc[mi][ni][2], -0.0078125f, cc0),
                             fmaf(acc[mi][ni][3], -0.0078125f, cc1));
            m0 = fminf(m0, __shfl_xor_sync(~0u, m0, 1));
            m0 = fminf(m0, __shfl_xor_sync(~0u, m0, 2));
            m8 = fminf(m8, __shfl_xor_sync(~0u, m8, 1));
            m8 = fminf(m8, __shfl_xor_sync(~0u, m8, 2));
            if ((l & 3) == 0) {
                size_t g = (size_t)((k0 + wn * 64 + ni * 8) >> 3);
                g_gmin[g * NQ + q0 + rl0] = m0;
                g_gmin[g * NQ + q0 + rl0 + 8] = m8;
                rmin0 = fminf(rmin0, m0);
                rmin8 = fminf(rmin8, m8);
            }
        }
        if ((l & 3) == 0) {
            atomicMin(&srowmin[rl0], fenc(rmin0));
            atomicMin(&srowmin[rl0 + 8], fenc(rmin8));
        }
    }
    __syncthreads();
    if (tid < PM) atomicMin(&g_m1[q0 + tid], srowmin[tid]);
}

// ---------------------------------------------------------------------------
// Phase 2a: flag groups with v <= m1 + EPS (single pass; m1 from phase1).
__global__ void __launch_bounds__(256) cand_kernel() {
    int q0 = blockIdx.x * 32;
    int wid = threadIdx.x >> 5, l = threadIdx.x & 31;
    int q = q0 + l;
    float thr = fdec(g_m1[q]) + EPS;
    for (int g = wid; g < NGRP; g += 8) {
        if (g_gmin[(size_t)g * NQ + q] <= thr) {
            int pos = atomicAdd(&g_ncand, 1);
            if (pos < CAND_CAP) g_cand[pos] = ((unsigned)q << 10) | (unsigned)g;
        }
    }
}

// Phase 2b: exact fp32 rescore of flagged groups; packed atomicMin => argmin
// with first-index tie-break (reference rounding formula, R1-validated).
__global__ void __launch_bounds__(256) rescore_kernel(const float* __restrict__ cb) {
    int gw = (blockIdx.x * blockDim.x + threadIdx.x) >> 5;
    int l = threadIdx.x & 31;
    int nwarps = (gridDim.x * blockDim.x) >> 5;
    int n = g_ncand; if (n > CAND_CAP) n = CAND_CAP;
    for (int c = gw; c < n; c += nwarps) {
        unsigned e = g_cand[c];
        int q = e >> 10, g = e & 1023;
        const float* zr = g_zt + (size_t)q * Dd;
        float zzv = g_zz[q];
        unsigned long long best = ~0ull;
        #pragma unroll 1
        for (int kk = 0; kk < 8; kk++) {
            int k = g * 8 + kk;
            const float* cr = cb + (size_t)k * Dd;
            float p = 0.0f;
            #pragma unroll
            for (int j = 0; j < 8; j++) {
                int d = l * 8 + j;
                p = __fadd_rn(p, __fmul_rn(zr[d], cr[d]));
            }
            #pragma unroll
            for (int o = 16; o > 0; o >>= 1)
                p = __fadd_rn(p, __shfl_xor_sync(~0u, p, o));
            float dd = __fadd_rn(__fadd_rn(zzv, __fmul_rn(-2.0f, p)), g_cc[k]);
            unsigned long long key =
                ((unsigned long long)__float_as_uint(dd) << 32) | (unsigned)k;
            if (key < best) best = key;
        }
        if (l == 0) atomicMin(&g_key[q], best);
    }
}

// ---------------------------------------------------------------------------
// Gather: coalesced via smem transpose of the gathered codebook rows.
__global__ void gather_kernel(const float* __restrict__ z,
                              const float* __restrict__ cb,
                              float* __restrict__ out, long long out_size) {
    __shared__ float tile[32][33];
    __shared__ double ssum[256];
    int b = blockIdx.z, d0 = blockIdx.y * 32, t0 = blockIdx.x * 32;
    int tx = threadIdx.x, ty = threadIdx.y;
    #pragma unroll
    for (int r = 0; r < 4; r++) {
        int t = ty + r * 8;
        int q = b * Tt + t0 + t;
        int idx = (int)(unsigned)(g_key[q] & 0xffffffffu);
        tile[t][tx] = cb[(size_t)idx * Dd + d0 + tx];     // lane spans d: coalesced
    }
    __syncthreads();
    double local = 0.0;
    #pragma unroll
    for (int r = 0; r < 4; r++) {
        int d = d0 + ty + r * 8;
        long long o = ((long long)b * Dd + d) * Tt + t0 + tx;
        float zv = z[o];
        float zq = tile[tx][ty + r * 8];
        float diff = __fadd_rn(zq, -zv);
        if (o < out_size) out[o] = __fadd_rn(zv, diff);   // lane spans t: coalesced
        local += (double)__fmul_rn(diff, diff);
    }
    int tid = ty * 32 + tx;
    ssum[tid] = local;
    __syncthreads();
    for (int s = 128; s > 0; s >>= 1) {
        if (tid < s) ssum[tid] += ssum[tid + s];
        __syncthreads();
    }
    if (tid == 0) atomicAdd(&g_loss_sum, ssum[0]);
}

__global__ void finalize_kernel(float* __restrict__ out, long long out_size) {
    int i = blockIdx.x * blockDim.x + threadIdx.x;
    if (out_size >= NEL + NQ && i < NQ)
        out[NEL + i] = (float)(unsigned)(g_key[i] & 0xffffffffu);
    if (i == 0 && out_size >= NEL + NQ + 1) {
        float m = (float)(g_loss_sum / (double)NEL);
        out[NEL + NQ] = __fadd_rn(m, __fmul_rn(0.1f, m));
    }
}

// ---------------------------------------------------------------------------
extern "C" void kernel_launch(void* const* d_in, const int* in_sizes, int n_in,
                              void* d_out, int out_size) {
    const float* z  = (const float*)d_in[0];
    const float* cb = (const float*)d_in[1];
    if (n_in >= 2 && in_sizes[0] == Kk * Dd && in_sizes[1] == NEL) {
        const float* tmp = z; z = cb; cb = tmp;
    }
    float* out = (float*)d_out;
    long long osz = out_size;

    cudaFuncSetAttribute(phase1_kernel,
                         cudaFuncAttributeMaxDynamicSharedMemorySize, SMEM_DYN);

    // phase1 kept at launch index 3 (the launch ncu captures)
    prep_cb_kernel<<<(Kk * Dd + 255) / 256, 256>>>(cb);                 // 0
    dim3 tb(32, 8), tg(Tt / 32, Dd / 32, Bq);
    prep_z_kernel<<<tg, tb>>>(z);                                       // 1
    cc_init_kernel<<<(NQ + 255) / 256, 256>>>(cb);                      // 2
    dim3 g1(Kk / PN, NQ / PM);
    phase1_kernel<<<g1, 256, SMEM_DYN>>>();                             // 3
    zz_kernel<<<(NQ + 255) / 256, 256>>>(z);                            // 4
    cand_kernel<<<NQ / 32, 256>>>();                                    // 5
    rescore_kernel<<<512, 256>>>(cb);                                   // 6
    dim3 gg(Tt / 32, Dd / 32, Bq);
    gather_kernel<<<gg, tb>>>(z, cb, out, osz);                         // 7
    finalize_kernel<<<(NQ + 255) / 256, 256>>>(out, osz);               // 8
}

// round 8
// speedup vs baseline: 1.0606x; 1.0137x over previous
#include <cuda_runtime.h>
#include <cuda_fp16.h>
#include <cstdint>

// Problem constants
#define Bq 8
#define Dd 256
#define Tt 2048
#define Kk 8192
#define NQ (Bq * Tt)          // 16384 queries
#define NEL (Bq * Dd * Tt)    // 4194304 z elements
#define NGRP (Kk / 8)         // 1024 groups of 8 codes

#define EPS 0.006f
#define CAND_CAP (2 * 1024 * 1024)

// Phase-1 tiling
#define PM 128
#define PN 128
#define PK 64                 // gemm-K chunk
#define NCHUNK (Dd / PK)      // 4
#define ROWB 72               // smem row stride = 72 halves (64 data + 8 pad)
#define STAGE_BYTES ((PM + PN) * ROWB * 2)    // 36864
#define SMEM_DYN (2 * STAGE_BYTES)            // 73728

// Device scratch (static; runtime allocation is forbidden)
__device__ __align__(128) float  g_zt[NQ * Dd];     // z transposed [q][d] fp32
__device__ __align__(128) __half g_zhf[NQ * Dd];    // fp16 copy
__device__ __align__(128) __half g_cbhf[Kk * Dd];   // codebook * 256, fp16
__device__ __align__(128) float  g_gmin[(size_t)NGRP * NQ]; // per-(group,query) approx (cc-2dot)
__device__ __align__(128) unsigned g_m1[NQ];        // per-query encoded min of g_gmin
__device__ __align__(128) float  g_zz[NQ];
__device__ __align__(128) float  g_cc[Kk];
__device__ __align__(128) unsigned long long g_key[NQ];    // packed (dbits<<32)|k exact
__device__ __align__(128) unsigned int g_cand[CAND_CAP];   // (q<<10)|g
__device__ int    g_ncand;
__device__ double g_loss_sum;

// ---------------------------------------------------------------------------
__device__ __forceinline__ uint32_t smem_u32(const void* p) {
    uint32_t a;
    asm("{ .reg .u64 t; cvta.to.shared.u64 t, %1; cvt.u32.u64 %0, t; }" : "=r"(a) : "l"(p));
    return a;
}
// Order-preserving float<->uint encoding (monotone for all finite floats)
__device__ __forceinline__ unsigned fenc(float f) {
    int b = __float_as_int(f);
    return b >= 0 ? ((unsigned)b | 0x80000000u) : ~(unsigned)b;
}
__device__ __forceinline__ float fdec(unsigned k) {
    return (k & 0x80000000u) ? __int_as_float((int)(k & 0x7fffffffu))
                             : __int_as_float((int)~k);
}
#define CP16(dst, src) \
    asm volatile("cp.async.cg.shared.global [%0], [%1], 16;" :: "r"(dst), "l"(src) : "memory")
#define LDM4(r0, r1, r2, r3, a) \
    asm volatile("ldmatrix.sync.aligned.m8n8.x4.shared.b16 {%0,%1,%2,%3}, [%4];" \
        : "=r"(r0), "=r"(r1), "=r"(r2), "=r"(r3) : "r"(a))
#define MMA16816(c0, c1, c2, c3, a0, a1, a2, a3, b0, b1) \
    asm volatile("mma.sync.aligned.m16n8k16.row.col.f32.f16.f16.f32 " \
        "{%0,%1,%2,%3}, {%4,%5,%6,%7}, {%8,%9}, {%0,%1,%2,%3};" \
        : "+f"(c0), "+f"(c1), "+f"(c2), "+f"(c3) \
        : "r"(a0), "r"(a1), "r"(a2), "r"(a3), "r"(b0), "r"(b1))

// ---------------------------------------------------------------------------
// Exact sequential fp32 sums of squares (rounding order validated in R1)
__global__ void zz_kernel(const float* __restrict__ z) {
    int i = blockIdx.x * blockDim.x + threadIdx.x;
    if (i >= NQ) return;
    int b = i / Tt, t = i % Tt;
    const float* p = z + (size_t)b * Dd * Tt + t;
    float acc = 0.0f;
    for (int d = 0; d < Dd; d++) {
        float v = p[(size_t)d * Tt];
        acc = __fadd_rn(acc, __fmul_rn(v, v));
    }
    g_zz[i] = acc;
}

// cc (exact sequential) + global init fused
__global__ void cc_init_kernel(const float* __restrict__ cb) {
    int i = blockIdx.x * blockDim.x + threadIdx.x;
    if (i < Kk) {
        const float* p = cb + (size_t)i * Dd;
        float acc = 0.0f;
        for (int d = 0; d < Dd; d++) {
            float v = p[d];
            acc = __fadd_rn(acc, __fmul_rn(v, v));
        }
        g_cc[i] = acc;
    }
    if (i < NQ) { g_key[i] = ~0ull; g_m1[i] = 0xFFFFFFFFu; }
    if (i == 0) { g_loss_sum = 0.0; g_ncand = 0; }
}

// codebook * 256 (exact pow2 rescale into fp16's sweet spot)
__global__ void prep_cb_kernel(const float* __restrict__ cb) {
    int i = blockIdx.x * blockDim.x + threadIdx.x;
    if (i < Kk * Dd) g_cbhf[i] = __float2half(cb[i] * 256.0f);
}

// Transpose z (B,D,T) -> [q][d]; write fp32 + fp16 copies.
__global__ void prep_z_kernel(const float* __restrict__ z) {
    __shared__ float tile[32][33];
    int b = blockIdx.z, t0 = blockIdx.x * 32, d0 = blockIdx.y * 32;
    int tx = threadIdx.x, ty = threadIdx.y;   // 32 x 8
    #pragma unroll
    for (int r = 0; r < 4; r++) {
        int d = d0 + ty + r * 8;
        tile[ty + r * 8][tx] = z[(size_t)b * Dd * Tt + (size_t)d * Tt + t0 + tx];
    }
    __syncthreads();
    #pragma unroll
    for (int r = 0; r < 4; r++) {
        int tt = t0 + ty + r * 8;
        float v = tile[tx][ty + r * 8];
        size_t o = (size_t)(b * Tt + tt) * Dd + d0 + tx;
        g_zt[o] = v;
        g_zhf[o] = __float2half(v);
    }
}

// ---------------------------------------------------------------------------
// Phase 1: fp16 mma.sync GEMM, PK=64 chunks, 2-stage cp.async.
// WARP PHASE STAGGER: each warp walks the 4 k16-steps of a chunk in a
// rotated order (kk = (ks + wid) & 3), so at any instant some warps are in
// their ldmatrix phase while others run MMAs -> LDS and tensor pipes overlap
// instead of alternating (R5-R7 showed both pinned at ~46%, serialized).
__global__ void __launch_bounds__(256, 2) phase1_kernel() {
    extern __shared__ __half smh[];
    __shared__ unsigned srowmin[PM];

    int tid = threadIdx.x, wid = tid >> 5, l = tid & 31;
    int wm = wid & 3, wn = wid >> 2;
    int q0 = blockIdx.y * PM, k0 = blockIdx.x * PN;

    if (tid < PM) srowmin[tid] = 0xFFFFFFFFu;

    float acc[2][8][4];
    #pragma unroll
    for (int mi = 0; mi < 2; mi++)
        #pragma unroll
        for (int ni = 0; ni < 8; ni++)
            #pragma unroll
            for (int j = 0; j < 4; j++) acc[mi][ni][j] = 0.0f;

    uint32_t s0 = smem_u32(&smh[0]);
    const uint32_t bOffB = (uint32_t)PM * ROWB * 2;

    int rA = wm * 32 + (l & 15), hA = (l >> 4) & 1;
    int rB = wn * 64 + (l & 15), hB = (l >> 4) & 1;
    uint32_t aoff = (uint32_t)(rA * ROWB + hA * 8) * 2;
    uint32_t boff = (uint32_t)(rB * ROWB + hB * 8) * 2;
    int rot = wid & 3;                       // per-warp k16-phase rotation

    auto issue = [&](int c) {
        uint32_t st = s0 + (uint32_t)(c & 1) * STAGE_BYTES;
        int d0 = c * PK;
        #pragma unroll
        for (int i = 0; i < 8; i++) {
            int idx = tid + i * 256;          // 0..2047
            int row = idx >> 3, sec = idx & 7;
            const __half* src = (row < PM)
                ? g_zhf + (size_t)(q0 + row) * Dd + d0 + sec * 8
                : g_cbhf + (size_t)(k0 + row - PM) * Dd + d0 + sec * 8;
            uint32_t dst = st + ((row < PM)
                ? (uint32_t)(row * ROWB + sec * 8) * 2
                : (bOffB + (uint32_t)((row - PM) * ROWB + sec * 8) * 2));
            CP16(dst, src);
        }
        asm volatile("cp.async.commit_group;" ::: "memory");
    };

    issue(0);
    for (int c = 0; c < NCHUNK; c++) {
        if (c + 1 < NCHUNK) {
            issue(c + 1);
            asm volatile("cp.async.wait_group 1;" ::: "memory");
        } else {
            asm volatile("cp.async.wait_group 0;" ::: "memory");
        }
        __syncthreads();
        uint32_t st = s0 + (uint32_t)(c & 1) * STAGE_BYTES;
        uint32_t bA = st, bB = st + bOffB;
        #pragma unroll
        for (int ks = 0; ks < 4; ks++) {
            int kk = (ks + rot) & 3;               // staggered k16 step
            uint32_t kb = (uint32_t)(kk * 16) * 2; // byte offset of the slice
            uint32_t af[2][4], bf[4][4];
            #pragma unroll
            for (int mi = 0; mi < 2; mi++)
                LDM4(af[mi][0], af[mi][1], af[mi][2], af[mi][3],
                     bA + aoff + (uint32_t)(mi * 16 * ROWB) * 2 + kb);
            #pragma unroll
            for (int p = 0; p < 4; p++)
                LDM4(bf[p][0], bf[p][1], bf[p][2], bf[p][3],
                     bB + boff + (uint32_t)(p * 16 * ROWB) * 2 + kb);
            #pragma unroll
            for (int mi = 0; mi < 2; mi++)
                #pragma unroll
                for (int p = 0; p < 4; p++) {
                    MMA16816(acc[mi][2*p][0], acc[mi][2*p][1], acc[mi][2*p][2], acc[mi][2*p][3],
                             af[mi][0], af[mi][1], af[mi][2], af[mi][3],
                             bf[p][0], bf[p][2]);
                    MMA16816(acc[mi][2*p+1][0], acc[mi][2*p+1][1], acc[mi][2*p+1][2], acc[mi][2*p+1][3],
                             af[mi][0], af[mi][1], af[mi][2], af[mi][3],
                             bf[p][1], bf[p][3]);
                }
        }
        __syncthreads();
    }

    // Epilogue: v = cc - 2*dot = fma(acc, -2^-7, cc)  (acc = dot*256)
    int gq = l >> 2;
    #pragma unroll
    for (int mi = 0; mi < 2; mi++) {
        int rl0 = wm * 32 + mi * 16 + gq;
        float rmin0 = 3.4e38f, rmin8 = 3.4e38f;
        #pragma unroll
        for (int ni = 0; ni < 8; ni++) {
            int col = k0 + wn * 64 + ni * 8 + (l & 3) * 2;
            float cc0 = g_cc[col], cc1 = g_cc[col + 1];
            float m0 = fminf(fmaf(acc[mi][ni][0], -0.0078125f, cc0),
                             fmaf(acc[mi][ni][1], -0.0078125f, cc1));
            float m8 = fminf(fmaf(acc[mi][ni][2], -0.0078125f, cc0),
                             fmaf(acc[mi][ni][3], -0.0078125f, cc1));
            m0 = fminf(m0, __shfl_xor_sync(~0u, m0, 1));
            m0 = fminf(m0, __shfl_xor_sync(~0u, m0, 2));
            m8 = fminf(m8, __shfl_xor_sync(~0u, m8, 1));
            m8 = fminf(m8, __shfl_xor_sync(~0u, m8, 2));
            if ((l & 3) == 0) {
                size_t g = (size_t)((k0 + wn * 64 + ni * 8) >> 3);
                g_gmin[g * NQ + q0 + rl0] = m0;
                g_gmin[g * NQ + q0 + rl0 + 8] = m8;
                rmin0 = fminf(rmin0, m0);
                rmin8 = fminf(rmin8, m8);
            }
        }
        if ((l & 3) == 0) {
            atomicMin(&srowmin[rl0], fenc(rmin0));
            atomicMin(&srowmin[rl0 + 8], fenc(rmin8));
        }
    }
    __syncthreads();
    if (tid < PM) atomicMin(&g_m1[q0 + tid], srowmin[tid]);
}

// ---------------------------------------------------------------------------
// Phase 2a: flag groups with v <= m1 + EPS (single pass; m1 from phase1).
__global__ void __launch_bounds__(256) cand_kernel() {
    int q0 = blockIdx.x * 32;
    int wid = threadIdx.x >> 5, l = threadIdx.x & 31;
    int q = q0 + l;
    float thr = fdec(g_m1[q]) + EPS;
    for (int g = wid; g < NGRP; g += 8) {
        if (g_gmin[(size_t)g * NQ + q] <= thr) {
            int pos = atomicAdd(&g_ncand, 1);
            if (pos < CAND_CAP) g_cand[pos] = ((unsigned)q << 10) | (unsigned)g;
        }
    }
}

// Phase 2b: exact fp32 rescore of flagged groups; packed atomicMin => argmin
// with first-index tie-break (reference rounding formula, R1-validated).
__global__ void __launch_bounds__(256) rescore_kernel(const float* __restrict__ cb) {
    int gw = (blockIdx.x * blockDim.x + threadIdx.x) >> 5;
    int l = threadIdx.x & 31;
    int nwarps = (gridDim.x * blockDim.x) >> 5;
    int n = g_ncand; if (n > CAND_CAP) n = CAND_CAP;
    for (int c = gw; c < n; c += nwarps) {
        unsigned e = g_cand[c];
        int q = e >> 10, g = e & 1023;
        const float* zr = g_zt + (size_t)q * Dd;
        float zzv = g_zz[q];
        unsigned long long best = ~0ull;
        #pragma unroll 1
        for (int kk = 0; kk < 8; kk++) {
            int k = g * 8 + kk;
            const float* cr = cb + (size_t)k * Dd;
            float p = 0.0f;
            #pragma unroll
            for (int j = 0; j < 8; j++) {
                int d = l * 8 + j;
                p = __fadd_rn(p, __fmul_rn(zr[d], cr[d]));
            }
            #pragma unroll
            for (int o = 16; o > 0; o >>= 1)
                p = __fadd_rn(p, __shfl_xor_sync(~0u, p, o));
            float dd = __fadd_rn(__fadd_rn(zzv, __fmul_rn(-2.0f, p)), g_cc[k]);
            unsigned long long key =
                ((unsigned long long)__float_as_uint(dd) << 32) | (unsigned)k;
            if (key < best) best = key;
        }
        if (l == 0) atomicMin(&g_key[q], best);
    }
}

// ---------------------------------------------------------------------------
// Gather: coalesced via smem transpose of the gathered codebook rows.
__global__ void gather_kernel(const float* __restrict__ z,
                              const float* __restrict__ cb,
                              float* __restrict__ out, long long out_size) {
    __shared__ float tile[32][33];
    __shared__ double ssum[256];
    int b = blockIdx.z, d0 = blockIdx.y * 32, t0 = blockIdx.x * 32;
    int tx = threadIdx.x, ty = threadIdx.y;
    #pragma unroll
    for (int r = 0; r < 4; r++) {
        int t = ty + r * 8;
        int q = b * Tt + t0 + t;
        int idx = (int)(unsigned)(g_key[q] & 0xffffffffu);
        tile[t][tx] = cb[(size_t)idx * Dd + d0 + tx];     // lane spans d: coalesced
    }
    __syncthreads();
    double local = 0.0;
    #pragma unroll
    for (int r = 0; r < 4; r++) {
        int d = d0 + ty + r * 8;
        long long o = ((long long)b * Dd + d) * Tt + t0 + tx;
        float zv = z[o];
        float zq = tile[tx][ty + r * 8];
        float diff = __fadd_rn(zq, -zv);
        if (o < out_size) out[o] = __fadd_rn(zv, diff);   // lane spans t: coalesced
        local += (double)__fmul_rn(diff, diff);
    }
    int tid = ty * 32 + tx;
    ssum[tid] = local;
    __syncthreads();
    for (int s = 128; s > 0; s >>= 1) {
        if (tid < s) ssum[tid] += ssum[tid + s];
        __syncthreads();
    }
    if (tid == 0) atomicAdd(&g_loss_sum, ssum[0]);
}

__global__ void finalize_kernel(float* __restrict__ out, long long out_size) {
    int i = blockIdx.x * blockDim.x + threadIdx.x;
    if (out_size >= NEL + NQ && i < NQ)
        out[NEL + i] = (float)(unsigned)(g_key[i] & 0xffffffffu);
    if (i == 0 && out_size >= NEL + NQ + 1) {
        float m = (float)(g_loss_sum / (double)NEL);
        out[NEL + NQ] = __fadd_rn(m, __fmul_rn(0.1f, m));
    }
}

// ---------------------------------------------------------------------------
extern "C" void kernel_launch(void* const* d_in, const int* in_sizes, int n_in,
                              void* d_out, int out_size) {
    const float* z  = (const float*)d_in[0];
    const float* cb = (const float*)d_in[1];
    if (n_in >= 2 && in_sizes[0] == Kk * Dd && in_sizes[1] == NEL) {
        const float* tmp = z; z = cb; cb = tmp;
    }
    float* out = (float*)d_out;
    long long osz = out_size;

    cudaFuncSetAttribute(phase1_kernel,
                         cudaFuncAttributeMaxDynamicSharedMemorySize, SMEM_DYN);

    // phase1 kept at launch index 3 (the launch ncu captures)
    prep_cb_kernel<<<(Kk * Dd + 255) / 256, 256>>>(cb);                 // 0
    dim3 tb(32, 8), tg(Tt / 32, Dd / 32, Bq);
    prep_z_kernel<<<tg, tb>>>(z);                                       // 1
    cc_init_kernel<<<(NQ + 255) / 256, 256>>>(cb);                      // 2
    dim3 g1(Kk / PN, NQ / PM);
    phase1_kernel<<<g1, 256, SMEM_DYN>>>();                             // 3
    zz_kernel<<<(NQ + 255) / 256, 256>>>(z);                            // 4
    cand_kernel<<<NQ / 32, 256>>>();                                    // 5
    rescore_kernel<<<512, 256>>>(cb);                                   // 6
    dim3 gg(Tt / 32, Dd / 32, Bq);
    gather_kernel<<<gg, tb>>>(z, cb, out, osz);                         // 7
    finalize_kernel<<<(NQ + 255) / 256, 256>>>(out, osz);               // 8
}